// round 15
// baseline (speedup 1.0000x reference)
#include <cuda_runtime.h>
#include <math.h>

#define N_NODES_C 100000
#define N_PATHS_C 1000000
#define T_C 16
#define F_C 9

#define QSCALE 16384.0f
#define QINV   (1.0f / 16384.0f)

// Node record: 16 x int16 (32B, one L2 sector): [0..8]=Re(log X_f)*2^14,
// [9..15]=Im(log X_f)*2^14 for f=1..7. 32B-aligned -> never straddles a line.
__device__ int2 g_tab[N_NODES_C * 4];     // record n = g_tab[4n .. 4n+3]

// ---------------------------------------------------------------------------
// Compile-time twiddles: cos(pi*k/8), sin(pi*k/8). Folds to FFMA immediates.
// ---------------------------------------------------------------------------
__device__ __forceinline__ float COSPI16(int k) {
    switch (((k % 16) + 16) & 15) {
        case 0:  return  1.0f;
        case 1:  return  0.9238795325112867f;
        case 2:  return  0.7071067811865476f;
        case 3:  return  0.3826834323650898f;
        case 4:  return  0.0f;
        case 5:  return -0.3826834323650898f;
        case 6:  return -0.7071067811865476f;
        case 7:  return -0.9238795325112867f;
        case 8:  return -1.0f;
        case 9:  return -0.9238795325112867f;
        case 10: return -0.7071067811865476f;
        case 11: return -0.3826834323650898f;
        case 12: return  0.0f;
        case 13: return  0.3826834323650898f;
        case 14: return  0.7071067811865476f;
        default: return  0.9238795325112867f;
    }
}
__device__ __forceinline__ float SINPI16(int k) { return COSPI16(k - 4); }

__device__ __forceinline__ int q16(float v) {
    int x = __float2int_rn(v * QSCALE);
    x = max(-32768, min(32767, x));
    return x;
}
__device__ __forceinline__ int pack16(int a, int b) {
    return (a & 0xFFFF) | (b << 16);
}

// ---------------------------------------------------------------------------
// Kernel A: per-node log-spectrum via geometric closed form, int16-quantized,
// 32B per node.
// ---------------------------------------------------------------------------
#define NODE_TPB 256

__global__ __launch_bounds__(NODE_TPB)
void node_irf_kernel(const float* __restrict__ params, int n_nodes) {
    int n = blockIdx.x * NODE_TPB + threadIdx.x;
    if (n >= n_nodes) return;

    float k = params[n] + 0.5f;
    float inv_k = 1.0f / k;
    float r = __expf(-inv_k);
    float r2 = r * r, r4 = r2 * r2, r8 = r4 * r4, r16 = r8 * r8;
    float C = __logf(inv_k * (1.0f - r16));

    int q[16];
    q[0] = q16(C - __logf(1.0f - r));       // f=0
    q[8] = q16(C - __logf(1.0f + r));       // f=8 (Nyquist)
#pragma unroll
    for (int f = 1; f <= 7; f++) {
        float dre = 1.0f - r * COSPI16(f);
        float dim = r * SINPI16(f);
        q[f]     = q16(C - 0.5f * __logf(dre * dre + dim * dim));
        q[8 + f] = q16(-atan2f(dim, dre));
    }

    int4* dst = reinterpret_cast<int4*>(&g_tab[n * 4]);
    dst[0] = make_int4(pack16(q[0],  q[1]),  pack16(q[2],  q[3]),
                       pack16(q[4],  q[5]),  pack16(q[6],  q[7]));
    dst[1] = make_int4(pack16(q[8],  q[9]),  pack16(q[10], q[11]),
                       pack16(q[12], q[13]), pack16(q[14], q[15]));
}

// ---------------------------------------------------------------------------
// lower_bound over sorted path_idxs: first i with arr[i] >= target.
// Only called with block-uniform targets -> warp-uniform, cache-hot.
// ---------------------------------------------------------------------------
__device__ __forceinline__ int lower_bound_g(const int* __restrict__ arr,
                                             int n, int target) {
    int lo = 0, hi = n;
    while (lo < hi) {
        int mid = (lo + hi) >> 1;
        if (__ldg(arr + mid) < target) lo = mid + 1;
        else hi = mid;
    }
    return lo;
}

// ---------------------------------------------------------------------------
// Kernel C (fused): Phase 0 — block range [lo,hi) via TWO block-uniform
// binary searches, then a coalesced linear scan of the range scattering
// lower_bound boundaries into smem (init hi; slot lp gets the first i with
// idx[i] >= block_base+lp). Deterministic: each slot's final value is a pure
// function of the data. Phase 1 — 4 lanes per path; lane j loads int2 slot j
// of the 32B record (one sector, one wavefront/record — the measured L1tex
// floor). Exact int32 accumulation. Phase 2 — one thread per path: dequant,
// complex exp (fast intrinsics), analytic 16-pt irfft, relu, flip, normalize.
// ---------------------------------------------------------------------------
#define AGG_TPB 128
#define PATHS_PER_BLK 128
#define CHUNK 8

__global__ __launch_bounds__(AGG_TPB, 8)
void agg_kernel(const int* __restrict__ path_idxs,
                const int* __restrict__ path_nodes,
                float* __restrict__ out, int e_total, int n_paths) {
    __shared__ int s_start[PATHS_PER_BLK + 1];
    __shared__ int s_acc[PATHS_PER_BLK][17];   // stride 17: conflict-free

    int tid = threadIdx.x;
    int block_base = blockIdx.x * PATHS_PER_BLK;

    // ---- Phase 0: block range + boundary scan ----
    int lo = lower_bound_g(path_idxs, e_total, block_base);
    int hi = lower_bound_g(path_idxs, e_total, block_base + PATHS_PER_BLK);

    if (tid <= PATHS_PER_BLK) s_start[tid] = hi;
    if (tid == 0 && AGG_TPB <= PATHS_PER_BLK) s_start[PATHS_PER_BLK] = hi;
    __syncthreads();

    for (int i = lo + tid; i < hi; i += AGG_TPB) {
        int v = __ldg(path_idxs + i) - block_base;              // 0..127
        int pv = (i == 0) ? -1 : (__ldg(path_idxs + i - 1) - block_base);
        int q0 = (pv + 1 > 0) ? pv + 1 : 0;
        for (int q = q0; q <= v; q++) s_start[q] = i;
    }
    __syncthreads();

    int j = tid & 3;     // int2 slot within 32B record
    int g = tid >> 2;    // quad id 0..31

    const int2* tab = g_tab;

    // ---- Phase 1: gather (4 sub-phases x 32 paths) ----
#pragma unroll
    for (int sp = 0; sp < 4; sp++) {
        int lp = sp * 32 + g;
        int p = block_base + lp;
        int a0 = 0, a1 = 0, a2 = 0, a3 = 0;
        if (p < n_paths) {
            int s = s_start[lp];
            int e = s_start[lp + 1];
            for (int i = s; i < e; i += CHUNK) {
                int nn[CHUNK];
#pragma unroll
                for (int kk = 0; kk < CHUNK; kk++) {
                    nn[kk] = (i + kk < e) ? __ldg(path_nodes + i + kk) : -1;
                }
                int2 vv[CHUNK];
#pragma unroll
                for (int kk = 0; kk < CHUNK; kk++) {
                    vv[kk] = (nn[kk] >= 0) ? __ldg(tab + nn[kk] * 4 + j)
                                           : make_int2(0, 0);
                }
#pragma unroll
                for (int kk = 0; kk < CHUNK; kk++) {
                    a0 += (int)(short)vv[kk].x;
                    a1 += vv[kk].x >> 16;
                    a2 += (int)(short)vv[kk].y;
                    a3 += vv[kk].y >> 16;
                }
            }
        }
        s_acc[lp][j * 4 + 0] = a0;
        s_acc[lp][j * 4 + 1] = a1;
        s_acc[lp][j * 4 + 2] = a2;
        s_acc[lp][j * 4 + 3] = a3;
    }
    __syncthreads();

    // ---- Phase 2: one thread per path ----
    int p = block_base + tid;
    if (p >= n_paths) return;

    float acc[16];
#pragma unroll
    for (int c = 0; c < 16; c++) acc[c] = (float)s_acc[tid][c] * QINV;

    // complex exp of aggregated logs (CASCADE = 1) — fast intrinsics.
    float Xr[F_C], Xi[F_C];
    Xr[0] = __expf(acc[0]);  Xi[0] = 0.0f;
    Xr[8] = __expf(acc[8]);  Xi[8] = 0.0f;
#pragma unroll
    for (int f = 1; f <= 7; f++) {
        float m = __expf(acc[f]);
        float si, co;
        __sincosf(acc[8 + f], &si, &co);
        Xr[f] = m * co;
        Xi[f] = m * si;
    }

    // irfft (n=16) with t <-> 16-t symmetry, constant twiddles.
    float x[T_C];
#pragma unroll
    for (int t = 0; t <= 8; t++) {
        float cs = 0.0f, ss = 0.0f;
#pragma unroll
        for (int f = 1; f <= 7; f++) {
            cs += Xr[f] * COSPI16(f * t);
            ss += Xi[f] * SINPI16(f * t);
        }
        float base = Xr[0] + ((t & 1) ? -Xr[8] : Xr[8]);
        float v1 = (base + 2.0f * (cs - ss)) * 0.0625f;
        if (t == 0) {
            x[0] = v1;
        } else if (t == 8) {
            x[8] = v1;
        } else {
            x[t] = v1;
            x[16 - t] = (base + 2.0f * (cs + ss)) * 0.0625f;
        }
    }

    // relu + sum
    float sum = 0.0f;
#pragma unroll
    for (int t = 0; t < T_C; t++) {
        x[t] = fmaxf(x[t], 0.0f);
        sum += x[t];
    }
    float inv_sum = 1.0f / sum;

    // flip + normalize, coalesced float4 stores
    float4* o4 = reinterpret_cast<float4*>(out + (size_t)p * 16);
    o4[0] = make_float4(x[15] * inv_sum, x[14] * inv_sum, x[13] * inv_sum, x[12] * inv_sum);
    o4[1] = make_float4(x[11] * inv_sum, x[10] * inv_sum, x[9]  * inv_sum, x[8]  * inv_sum);
    o4[2] = make_float4(x[7]  * inv_sum, x[6]  * inv_sum, x[5]  * inv_sum, x[4]  * inv_sum);
    o4[3] = make_float4(x[3]  * inv_sum, x[2]  * inv_sum, x[1]  * inv_sum, x[0]  * inv_sum);
}

// ---------------------------------------------------------------------------
extern "C" void kernel_launch(void* const* d_in, const int* in_sizes, int n_in,
                              void* d_out, int out_size) {
    const float* params     = (const float*)d_in[0];
    const int*   path_idxs  = (const int*)d_in[1];
    const int*   path_nodes = (const int*)d_in[2];
    float*       out        = (float*)d_out;

    int n_nodes = in_sizes[0];
    int e_total = in_sizes[1];
    int n_paths = out_size / T_C;
    if (n_nodes > N_NODES_C) n_nodes = N_NODES_C;
    if (n_paths > N_PATHS_C) n_paths = N_PATHS_C;

    node_irf_kernel<<<(n_nodes + NODE_TPB - 1) / NODE_TPB, NODE_TPB>>>(params, n_nodes);
    agg_kernel<<<(n_paths + PATHS_PER_BLK - 1) / PATHS_PER_BLK, AGG_TPB>>>(
        path_idxs, path_nodes, out, e_total, n_paths);
}

// round 16
// speedup vs baseline: 1.3269x; 1.3269x over previous
#include <cuda_runtime.h>
#include <math.h>

#define N_NODES_C 100000
#define N_PATHS_C 1000000
#define T_C 16
#define F_C 9

#define QSCALE 16384.0f
#define QINV   (1.0f / 16384.0f)

// Node record: 16 x int16 (32B, one L2 sector): [0..8]=Re(log X_f)*2^14,
// [9..15]=Im(log X_f)*2^14 for f=1..7. 32B-aligned -> never straddles a line.
__device__ int2 g_tab[N_NODES_C * 4];     // record n = g_tab[4n .. 4n+3]

// ---------------------------------------------------------------------------
// Compile-time twiddles: cos(pi*k/8), sin(pi*k/8). Folds to FFMA immediates.
// ---------------------------------------------------------------------------
__device__ __forceinline__ float COSPI16(int k) {
    switch (((k % 16) + 16) & 15) {
        case 0:  return  1.0f;
        case 1:  return  0.9238795325112867f;
        case 2:  return  0.7071067811865476f;
        case 3:  return  0.3826834323650898f;
        case 4:  return  0.0f;
        case 5:  return -0.3826834323650898f;
        case 6:  return -0.7071067811865476f;
        case 7:  return -0.9238795325112867f;
        case 8:  return -1.0f;
        case 9:  return -0.9238795325112867f;
        case 10: return -0.7071067811865476f;
        case 11: return -0.3826834323650898f;
        case 12: return  0.0f;
        case 13: return  0.3826834323650898f;
        case 14: return  0.7071067811865476f;
        default: return  0.9238795325112867f;
    }
}
__device__ __forceinline__ float SINPI16(int k) { return COSPI16(k - 4); }

__device__ __forceinline__ int q16(float v) {
    int x = __float2int_rn(v * QSCALE);
    x = max(-32768, min(32767, x));
    return x;
}
__device__ __forceinline__ int pack16(int a, int b) {
    return (a & 0xFFFF) | (b << 16);
}

// ---------------------------------------------------------------------------
// Kernel A: per-node log-spectrum via geometric closed form, int16-quantized,
// 32B per node.
// ---------------------------------------------------------------------------
#define NODE_TPB 256

__global__ __launch_bounds__(NODE_TPB)
void node_irf_kernel(const float* __restrict__ params, int n_nodes) {
    int n = blockIdx.x * NODE_TPB + threadIdx.x;
    if (n >= n_nodes) return;

    float k = params[n] + 0.5f;
    float inv_k = 1.0f / k;
    float r = __expf(-inv_k);
    float r2 = r * r, r4 = r2 * r2, r8 = r4 * r4, r16 = r8 * r8;
    float C = __logf(inv_k * (1.0f - r16));

    int q[16];
    q[0] = q16(C - __logf(1.0f - r));       // f=0
    q[8] = q16(C - __logf(1.0f + r));       // f=8 (Nyquist)
#pragma unroll
    for (int f = 1; f <= 7; f++) {
        float dre = 1.0f - r * COSPI16(f);
        float dim = r * SINPI16(f);
        q[f]     = q16(C - 0.5f * __logf(dre * dre + dim * dim));
        q[8 + f] = q16(-atan2f(dim, dre));
    }

    int4* dst = reinterpret_cast<int4*>(&g_tab[n * 4]);
    dst[0] = make_int4(pack16(q[0],  q[1]),  pack16(q[2],  q[3]),
                       pack16(q[4],  q[5]),  pack16(q[6],  q[7]));
    dst[1] = make_int4(pack16(q[8],  q[9]),  pack16(q[10], q[11]),
                       pack16(q[12], q[13]), pack16(q[14], q[15]));
}

// ---------------------------------------------------------------------------
// Warp-parallel 32-ary lower_bound: first i with arr[i] >= target.
// Each round issues 32 concurrent probes and shrinks the range 32x ->
// ~6 dependent memory rounds for n=8M (vs 23 for scalar bisection).
// All lanes return the same value.
// ---------------------------------------------------------------------------
__device__ __forceinline__ int warp_lower_bound(const int* __restrict__ arr,
                                                int n, int target) {
    int lane = threadIdx.x & 31;
    int lo = 0, hi = n;            // answer in [lo, hi]
    while (hi - lo > 32) {
        long long span = hi - lo;
        // probes strictly inside (lo, hi): pos(l) = lo + 1 + (span-1)*l/32
        int pos = lo + 1 + (int)(((span - 1) * lane) >> 5);
        bool pred = __ldg(arr + pos) < target;      // monotone over lanes
        unsigned bal = __ballot_sync(0xffffffffu, pred);
        int c = __popc(bal);
        if (c == 0) {
            hi = lo + 1;                            // pos(0)
        } else if (c == 32) {
            lo = lo + 1 + (int)(((span - 1) * 31) >> 5) + 1;   // pos(31)+1
        } else {
            int pl = lo + 1 + (int)(((span - 1) * (c - 1)) >> 5);  // pos(c-1)
            int pc = lo + 1 + (int)(((span - 1) * c) >> 5);        // pos(c)
            lo = pl + 1;
            hi = pc;
        }
    }
    // final: lanes probe [lo, hi) directly
    int pos = lo + lane;
    bool pred = (pos < hi) && (__ldg(arr + pos) < target);
    unsigned bal = __ballot_sync(0xffffffffu, pred);
    return lo + __popc(bal);
}

// ---------------------------------------------------------------------------
// Kernel C (fused): Phase 0 — warps 0/1 concurrently find the block's entry
// range [lo,hi) via warp-parallel 32-ary search (~6 dependent rounds each),
// then all threads scan the range coalesced, scattering lower_bound
// boundaries into smem (init hi). Deterministic: each slot's final value is
// a pure function of the sorted data. Phase 1 — 4 lanes per path; lane j
// loads int2 slot j of the 32B record (one sector/one wavefront per record —
// the measured L1tex floor). Exact int32 accumulation. Phase 2 — one thread
// per path: dequant, complex exp (fast intrinsics), analytic 16-pt irfft,
// relu, flip, normalize.
// ---------------------------------------------------------------------------
#define AGG_TPB 128
#define PATHS_PER_BLK 128
#define CHUNK 8

__global__ __launch_bounds__(AGG_TPB, 8)
void agg_kernel(const int* __restrict__ path_idxs,
                const int* __restrict__ path_nodes,
                float* __restrict__ out, int e_total, int n_paths) {
    __shared__ int s_range[2];
    __shared__ int s_start[PATHS_PER_BLK + 1];
    __shared__ int s_acc[PATHS_PER_BLK][17];   // stride 17: conflict-free

    int tid = threadIdx.x;
    int wid = tid >> 5;
    int block_base = blockIdx.x * PATHS_PER_BLK;

    // ---- Phase 0a: block range via two concurrent warp searches ----
    if (wid == 0) {
        int v = warp_lower_bound(path_idxs, e_total, block_base);
        if ((tid & 31) == 0) s_range[0] = v;
    } else if (wid == 1) {
        int v = warp_lower_bound(path_idxs, e_total, block_base + PATHS_PER_BLK);
        if ((tid & 31) == 0) s_range[1] = v;
    }
    __syncthreads();
    int lo = s_range[0];
    int hi = s_range[1];

    // ---- Phase 0b: boundary scan (coalesced, L1-hot) ----
    s_start[tid] = hi;
    if (tid == 0) s_start[PATHS_PER_BLK] = hi;
    __syncthreads();

    for (int i = lo + tid; i < hi; i += AGG_TPB) {
        int v = __ldg(path_idxs + i) - block_base;               // 0..127
        int pv = (i == 0) ? -1 : (__ldg(path_idxs + i - 1) - block_base);
        int q0 = (pv + 1 > 0) ? pv + 1 : 0;
        for (int q = q0; q <= v; q++) s_start[q] = i;
    }
    __syncthreads();

    int j = tid & 3;     // int2 slot within 32B record
    int g = tid >> 2;    // quad id 0..31

    const int2* tab = g_tab;

    // ---- Phase 1: gather (4 sub-phases x 32 paths) ----
#pragma unroll
    for (int sp = 0; sp < 4; sp++) {
        int lp = sp * 32 + g;
        int p = block_base + lp;
        int a0 = 0, a1 = 0, a2 = 0, a3 = 0;
        if (p < n_paths) {
            int s = s_start[lp];
            int e = s_start[lp + 1];
            for (int i = s; i < e; i += CHUNK) {
                int nn[CHUNK];
#pragma unroll
                for (int kk = 0; kk < CHUNK; kk++) {
                    nn[kk] = (i + kk < e) ? __ldg(path_nodes + i + kk) : -1;
                }
                int2 vv[CHUNK];
#pragma unroll
                for (int kk = 0; kk < CHUNK; kk++) {
                    vv[kk] = (nn[kk] >= 0) ? __ldg(tab + nn[kk] * 4 + j)
                                           : make_int2(0, 0);
                }
#pragma unroll
                for (int kk = 0; kk < CHUNK; kk++) {
                    a0 += (int)(short)vv[kk].x;
                    a1 += vv[kk].x >> 16;
                    a2 += (int)(short)vv[kk].y;
                    a3 += vv[kk].y >> 16;
                }
            }
        }
        s_acc[lp][j * 4 + 0] = a0;
        s_acc[lp][j * 4 + 1] = a1;
        s_acc[lp][j * 4 + 2] = a2;
        s_acc[lp][j * 4 + 3] = a3;
    }
    __syncthreads();

    // ---- Phase 2: one thread per path ----
    int p = block_base + tid;
    if (p >= n_paths) return;

    float acc[16];
#pragma unroll
    for (int c = 0; c < 16; c++) acc[c] = (float)s_acc[tid][c] * QINV;

    // complex exp of aggregated logs (CASCADE = 1) — fast intrinsics.
    float Xr[F_C], Xi[F_C];
    Xr[0] = __expf(acc[0]);  Xi[0] = 0.0f;
    Xr[8] = __expf(acc[8]);  Xi[8] = 0.0f;
#pragma unroll
    for (int f = 1; f <= 7; f++) {
        float m = __expf(acc[f]);
        float si, co;
        __sincosf(acc[8 + f], &si, &co);
        Xr[f] = m * co;
        Xi[f] = m * si;
    }

    // irfft (n=16) with t <-> 16-t symmetry, constant twiddles.
    float x[T_C];
#pragma unroll
    for (int t = 0; t <= 8; t++) {
        float cs = 0.0f, ss = 0.0f;
#pragma unroll
        for (int f = 1; f <= 7; f++) {
            cs += Xr[f] * COSPI16(f * t);
            ss += Xi[f] * SINPI16(f * t);
        }
        float base = Xr[0] + ((t & 1) ? -Xr[8] : Xr[8]);
        float v1 = (base + 2.0f * (cs - ss)) * 0.0625f;
        if (t == 0) {
            x[0] = v1;
        } else if (t == 8) {
            x[8] = v1;
        } else {
            x[t] = v1;
            x[16 - t] = (base + 2.0f * (cs + ss)) * 0.0625f;
        }
    }

    // relu + sum
    float sum = 0.0f;
#pragma unroll
    for (int t = 0; t < T_C; t++) {
        x[t] = fmaxf(x[t], 0.0f);
        sum += x[t];
    }
    float inv_sum = 1.0f / sum;

    // flip + normalize, coalesced float4 stores
    float4* o4 = reinterpret_cast<float4*>(out + (size_t)p * 16);
    o4[0] = make_float4(x[15] * inv_sum, x[14] * inv_sum, x[13] * inv_sum, x[12] * inv_sum);
    o4[1] = make_float4(x[11] * inv_sum, x[10] * inv_sum, x[9]  * inv_sum, x[8]  * inv_sum);
    o4[2] = make_float4(x[7]  * inv_sum, x[6]  * inv_sum, x[5]  * inv_sum, x[4]  * inv_sum);
    o4[3] = make_float4(x[3]  * inv_sum, x[2]  * inv_sum, x[1]  * inv_sum, x[0]  * inv_sum);
}

// ---------------------------------------------------------------------------
extern "C" void kernel_launch(void* const* d_in, const int* in_sizes, int n_in,
                              void* d_out, int out_size) {
    const float* params     = (const float*)d_in[0];
    const int*   path_idxs  = (const int*)d_in[1];
    const int*   path_nodes = (const int*)d_in[2];
    float*       out        = (float*)d_out;

    int n_nodes = in_sizes[0];
    int e_total = in_sizes[1];
    int n_paths = out_size / T_C;
    if (n_nodes > N_NODES_C) n_nodes = N_NODES_C;
    if (n_paths > N_PATHS_C) n_paths = N_PATHS_C;

    node_irf_kernel<<<(n_nodes + NODE_TPB - 1) / NODE_TPB, NODE_TPB>>>(params, n_nodes);
    agg_kernel<<<(n_paths + PATHS_PER_BLK - 1) / PATHS_PER_BLK, AGG_TPB>>>(
        path_idxs, path_nodes, out, e_total, n_paths);
}